// round 1
// baseline (speedup 1.0000x reference)
#include <cuda_runtime.h>
#include <cuda_bf16.h>

#define TT   65536
#define BB   4
#define W    16
#define NL   18
#define TILE 1024
#define HALO 512
#define NTHREADS 256

// Ping-pong hidden-state buffers, layout [B][T][W] (time-major, W contiguous)
__device__ float g_h0[(size_t)BB * TT * W];
__device__ float g_h1[(size_t)BB * TT * W];

__global__ void start_kernel(const float* __restrict__ x,
                             const float* __restrict__ sw,
                             float* __restrict__ out) {
    int idx = blockIdx.x * blockDim.x + threadIdx.x;  // over B*T
    if (idx < BB * TT) {
        float xv = x[idx];
        float s[W];
        #pragma unroll
        for (int o = 0; o < W; o++) s[o] = sw[o];
        #pragma unroll
        for (int o = 0; o < W; o++) g_h0[(size_t)idx * W + o] = s[o] * xv;
        out[idx] = 0.f;
    }
}

__global__ __launch_bounds__(NTHREADS, 1)
void layer_kernel(const float* __restrict__ cw, const float* __restrict__ cb,
                  const float* __restrict__ gw, const float* __restrict__ gb,
                  const float* __restrict__ rw, const float* __restrict__ rb,
                  const float* __restrict__ mix, float* __restrict__ out,
                  int li, int d, int last)
{
    extern __shared__ float sh[];  // (TILE+HALO) rows x W floats

    const float* hin  = (li & 1) ? g_h1 : g_h0;
    float*       hout = (li & 1) ? g_h0 : g_h1;

    const int b  = blockIdx.y;
    const int t0 = blockIdx.x * TILE;

    // Cooperative tile load (float4 vectorized; zero-fill causal pad t<0).
    {
        const int NELT4 = (TILE + HALO) * W / 4;
        const float4* src4 =
            reinterpret_cast<const float4*>(hin + ((size_t)b * TT + (t0 - HALO)) * W);
        float4* sh4 = reinterpret_cast<float4*>(sh);
        for (int i4 = threadIdx.x; i4 < NELT4; i4 += NTHREADS) {
            int t = t0 - HALO + (i4 * 4) / W;   // 4 floats never straddle a timestep (16%4==0)
            float4 v = make_float4(0.f, 0.f, 0.f, 0.f);
            if (t >= 0) v = src4[i4];
            sh4[i4] = v;
        }
    }

    const int o   = threadIdx.x & (W - 1);
    const int grp = threadIdx.x >> 4;   // 16 groups of 16 lanes

    // Per-lane weights in registers: lane o owns output channel o.
    float wc[3][W], wgt[3][W], wr[W];
    {
        const float* p = cw + ((size_t)(li * W + o) * W) * 3;
        #pragma unroll
        for (int i = 0; i < W; i++)
            #pragma unroll
            for (int k = 0; k < 3; k++) wc[k][i] = p[i * 3 + k];
        p = gw + ((size_t)(li * W + o) * W) * 3;
        #pragma unroll
        for (int i = 0; i < W; i++)
            #pragma unroll
            for (int k = 0; k < 3; k++) wgt[k][i] = p[i * 3 + k];
    }
    const float cb_o  = cb[li * W + o];
    const float gb_o  = gb[li * W + o];
    const float mix_o = mix[li * W + o];
    float rb_o = 0.f;
    if (!last) {
        const float* p = rw + (size_t)(li * W + o) * W;
        #pragma unroll
        for (int i = 0; i < W; i++) wr[i] = p[i];
        rb_o = rb[li * W + o];
    } else {
        #pragma unroll
        for (int i = 0; i < W; i++) wr[i] = 0.f;
    }

    __syncthreads();

    #pragma unroll 1
    for (int j = 0; j < TILE / 16; j++) {
        const int tl = HALO + grp + 16 * j;   // local smem row

        // Dilated causal conv taps: t-2d, t-d, t  (k = 0,1,2)
        float f0 = cb_o, f1 = 0.f, g0 = gb_o, g1 = 0.f;
        #pragma unroll
        for (int k = 0; k < 3; k++) {
            const float* hp = sh + (size_t)(tl - (2 - k) * d) * W;
            #pragma unroll
            for (int i = 0; i < W; i += 2) {
                float hv0 = hp[i];
                float hv1 = hp[i + 1];
                f0 += wc[k][i]     * hv0;
                g0 += wgt[k][i]    * hv0;
                f1 += wc[k][i + 1] * hv1;
                g1 += wgt[k][i + 1]* hv1;
            }
        }
        float f = f0 + f1;
        float g = g0 + g1;
        f = __fdividef(f, 1.f + fabsf(f));   // softsign
        g = __fdividef(g, 1.f + fabsf(g));
        const float z = f * g;

        // Mixer contribution: butterfly-reduce mix_o*z over the 16-lane segment.
        float m = mix_o * z;
        m += __shfl_xor_sync(0xFFFFFFFFu, m, 8, 16);
        m += __shfl_xor_sync(0xFFFFFFFFu, m, 4, 16);
        m += __shfl_xor_sync(0xFFFFFFFFu, m, 2, 16);
        m += __shfl_xor_sync(0xFFFFFFFFu, m, 1, 16);

        const int t = t0 + grp + 16 * j;
        const size_t oidx = (size_t)b * TT + t;
        if (o == 0) out[oidx] += m;

        if (!last) {
            // h_new[o] = h[o] + res_b[o] + sum_i res_w[o][i] * z_i
            float hn = sh[(size_t)tl * W + o] + rb_o;
            #pragma unroll
            for (int i = 0; i < W; i++) {
                float zi = __shfl_sync(0xFFFFFFFFu, z, i, 16);
                hn += wr[i] * zi;
            }
            hout[oidx * W + o] = hn;   // coalesced: warp writes 128B contiguous
        }
    }
}

extern "C" void kernel_launch(void* const* d_in, const int* in_sizes, int n_in,
                              void* d_out, int out_size) {
    const float* x   = (const float*)d_in[0];
    const float* sw  = (const float*)d_in[1];
    const float* cw  = (const float*)d_in[2];
    const float* cb  = (const float*)d_in[3];
    const float* gw  = (const float*)d_in[4];
    const float* gb  = (const float*)d_in[5];
    const float* rw  = (const float*)d_in[6];
    const float* rb  = (const float*)d_in[7];
    const float* mix = (const float*)d_in[8];
    float* out = (float*)d_out;

    static const int dil[NL] = {1,2,4,8,16,32,64,128,256,
                                1,2,4,8,16,32,64,128,256};

    const int smem = (TILE + HALO) * W * (int)sizeof(float);
    cudaFuncSetAttribute(layer_kernel,
                         cudaFuncAttributeMaxDynamicSharedMemorySize, smem);

    start_kernel<<<(BB * TT + 255) / 256, 256>>>(x, sw, out);

    dim3 grid(TT / TILE, BB);
    for (int li = 0; li < NL; li++) {
        layer_kernel<<<grid, NTHREADS, smem>>>(
            cw, cb, gw, gb, rw, rb, mix, out,
            li, dil[li], (li == NL - 1) ? 1 : 0);
    }
}

// round 2
// speedup vs baseline: 1.7175x; 1.7175x over previous
#include <cuda_runtime.h>
#include <cuda_bf16.h>

#define TT   65536
#define BB   4
#define W    16
#define NL   18
#define TILE2 512
#define NTH  256
#define HOFF 1856   // float offset of h tile in dynamic smem

typedef unsigned long long u64;

__device__ float g_h0[(size_t)BB * TT * W];
__device__ float g_h1[(size_t)BB * TT * W];

__device__ __forceinline__ u64 pk2(float x){ u64 r; asm("mov.b64 %0,{%1,%1};":"=l"(r):"f"(x)); return r; }
__device__ __forceinline__ u64 pk(float lo, float hi){ u64 r; asm("mov.b64 %0,{%1,%2};":"=l"(r):"f"(lo),"f"(hi)); return r; }
__device__ __forceinline__ void unpk(u64 v, float& lo, float& hi){ asm("mov.b64 {%0,%1},%2;":"=f"(lo),"=f"(hi):"l"(v)); }
__device__ __forceinline__ u64 fma2(u64 a, u64 b, u64 c){ u64 d; asm("fma.rn.f32x2 %0,%1,%2,%3;":"=l"(d):"l"(a),"l"(b),"l"(c)); return d; }
__device__ __forceinline__ u64 mul2(u64 a, u64 b){ u64 d; asm("mul.rn.f32x2 %0,%1,%2;":"=l"(d):"l"(a),"l"(b)); return d; }
__device__ __forceinline__ u64 add2(u64 a, u64 b){ u64 d; asm("add.rn.f32x2 %0,%1,%2;":"=l"(d):"l"(a),"l"(b)); return d; }
__device__ __forceinline__ float rcpf(float x){ float r; asm("rcp.approx.f32 %0,%1;":"=f"(r):"f"(x)); return r; }

#define ABS2 0x7FFFFFFF7FFFFFFFull
#define ONE2 0x3F8000003F800000ull

// z = softsign(f)*softsign(g) = f*g / ((1+|f|)(1+|g|)), packed over 2 channels
__device__ __forceinline__ u64 ssz(u64 f, u64 g){
    u64 df = add2(f & ABS2, ONE2);
    u64 dg = add2(g & ABS2, ONE2);
    u64 dd = mul2(df, dg);
    float dl, dh; unpk(dd, dl, dh);
    u64 rr = pk(rcpf(dl), rcpf(dh));
    return mul2(mul2(f, g), rr);
}

__global__ void start_kernel(const float* __restrict__ x,
                             const float* __restrict__ sw,
                             float* __restrict__ out) {
    int idx = blockIdx.x * blockDim.x + threadIdx.x;  // over B*T
    if (idx < BB * TT) {
        float xv = x[idx];
        #pragma unroll
        for (int o = 0; o < W; o++) g_h0[(size_t)idx * W + o] = sw[o] * xv;
        out[idx] = 0.f;
    }
}

// Dynamic smem layout (floats):
//  [0    :1536)  conv+gate weights, ((k*16+i)*32 + half*16 + o); half0=f, half1=g
//  [1536 :1792)  res weights transposed rsm[i][o]
//  [1792 :1808)  mixer msm[o]
//  [1808 :1824)  conv bias, [1824:1840) gate bias, [1840:1856) res bias
//  [1856 :    )  h tile, channel-major: hT[ch][R], R = TILE2 + 2d
__global__ __launch_bounds__(NTH, 1)
void layer2_kernel(const float* __restrict__ cw, const float* __restrict__ cb,
                   const float* __restrict__ gw, const float* __restrict__ gb,
                   const float* __restrict__ rw, const float* __restrict__ rb,
                   const float* __restrict__ mix, float* __restrict__ out,
                   int li, int d, int last)
{
    extern __shared__ float sh[];
    const float* hin  = (li & 1) ? g_h1 : g_h0;
    float*       hout = (li & 1) ? g_h0 : g_h1;
    const int b   = blockIdx.y;
    const int t0  = blockIdx.x * TILE2;
    const int tid = threadIdx.x;
    const int R   = TILE2 + 2 * d;
    float* hT = sh + HOFF;

    // ---- weight prep (once per block) ----
    for (int w = tid; w < 1536; w += NTH) {
        int k = w >> 9, rem = w & 511;
        int i = rem >> 5, half = (rem >> 4) & 1, o = rem & 15;
        const float* src = half ? gw : cw;
        sh[w] = src[li * 768 + o * 48 + i * 3 + k];
    }
    if (tid < 256) {
        int i = tid >> 4, o = tid & 15;
        sh[1536 + tid] = last ? 0.f : rw[li * 256 + o * 16 + i];
    }
    if (tid < 16) {
        sh[1792 + tid] = mix[li * 16 + tid];
        sh[1808 + tid] = cb[li * 16 + tid];
        sh[1824 + tid] = gb[li * 16 + tid];
        sh[1840 + tid] = last ? 0.f : rb[li * 16 + tid];
    }

    // ---- h tile load, transposing [t][ch] -> [ch][t] ----
    {
        const int n4 = R * 4;  // float4 chunks
        for (int idx = tid; idx < n4; idx += NTH) {
            int r = idx >> 2, c = idx & 3;
            int gt = t0 - 2 * d + r;
            float4 v = make_float4(0.f, 0.f, 0.f, 0.f);
            if (gt >= 0)
                v = *(const float4*)(hin + ((size_t)b * TT + gt) * W + 4 * c);
            hT[(4 * c + 0) * R + r] = v.x;
            hT[(4 * c + 1) * R + r] = v.y;
            hT[(4 * c + 2) * R + r] = v.z;
            hT[(4 * c + 3) * R + r] = v.w;
        }
    }
    __syncthreads();

    // ---- compute: this thread owns timesteps t0+tid and t0+tid+256 ----
    const int r0 = 2 * d + tid;          // local row of ts0; ts1 = r0 + 256

    u64 f0[8], f1[8], ga0[8], ga1[8];
    {
        const u64* bp = (const u64*)(sh + 1808);
        #pragma unroll
        for (int p = 0; p < 8; p++) {
            f0[p] = bp[p];     f1[p] = bp[p];
            ga0[p] = bp[8 + p]; ga1[p] = bp[8 + p];
        }
    }

    #pragma unroll 1
    for (int k = 0; k < 3; k++) {
        const int c = r0 - (2 - k) * d;
        #pragma unroll
        for (int i = 0; i < 16; i++) {
            float hv0 = hT[i * R + c];
            float hv1 = hT[i * R + c + 256];
            u64 hp0 = pk2(hv0), hp1 = pk2(hv1);
            const ulonglong2* wp = (const ulonglong2*)(sh) + (k * 16 + i) * 8;
            #pragma unroll
            for (int q = 0; q < 4; q++) {
                ulonglong2 wf = wp[q];
                ulonglong2 wg = wp[4 + q];
                f0[2*q]   = fma2(wf.x, hp0, f0[2*q]);
                f0[2*q+1] = fma2(wf.y, hp0, f0[2*q+1]);
                f1[2*q]   = fma2(wf.x, hp1, f1[2*q]);
                f1[2*q+1] = fma2(wf.y, hp1, f1[2*q+1]);
                ga0[2*q]   = fma2(wg.x, hp0, ga0[2*q]);
                ga0[2*q+1] = fma2(wg.y, hp0, ga0[2*q+1]);
                ga1[2*q]   = fma2(wg.x, hp1, ga1[2*q]);
                ga1[2*q+1] = fma2(wg.y, hp1, ga1[2*q+1]);
            }
        }
    }

    // ---- gated activation ----
    u64 z0[8], z1[8];
    #pragma unroll
    for (int p = 0; p < 8; p++) { z0[p] = ssz(f0[p], ga0[p]); z1[p] = ssz(f1[p], ga1[p]); }

    // ---- mixer: m = sum_o mix[o]*z[o], accumulate into out ----
    {
        const u64* mp = (const u64*)(sh + 1792);
        u64 m0 = mul2(mp[0], z0[0]);
        u64 m1 = mul2(mp[0], z1[0]);
        #pragma unroll
        for (int p = 1; p < 8; p++) { m0 = fma2(mp[p], z0[p], m0); m1 = fma2(mp[p], z1[p], m1); }
        float a0, b0, a1, b1; unpk(m0, a0, b0); unpk(m1, a1, b1);
        size_t ob = (size_t)b * TT + t0 + tid;
        out[ob]       += a0 + b0;
        out[ob + 256] += a1 + b1;
    }

    // ---- residual + write next h ----
    if (!last) {
        float zf0[16], zf1[16];
        #pragma unroll
        for (int p = 0; p < 8; p++) {
            unpk(z0[p], zf0[2*p], zf0[2*p+1]);
            unpk(z1[p], zf1[2*p], zf1[2*p+1]);
        }
        u64 hn0[8], hn1[8];
        {
            const u64* rbp = (const u64*)(sh + 1840);
            #pragma unroll
            for (int p = 0; p < 8; p++) {
                hn0[p] = add2(pk(hT[(2*p) * R + r0],       hT[(2*p+1) * R + r0]),       rbp[p]);
                hn1[p] = add2(pk(hT[(2*p) * R + r0 + 256], hT[(2*p+1) * R + r0 + 256]), rbp[p]);
            }
        }
        #pragma unroll
        for (int i = 0; i < 16; i++) {
            u64 zp0 = pk2(zf0[i]);
            u64 zp1 = pk2(zf1[i]);
            const ulonglong2* rp = (const ulonglong2*)(sh + 1536) + i * 4;
            #pragma unroll
            for (int q = 0; q < 4; q++) {
                ulonglong2 rr = rp[q];
                hn0[2*q]   = fma2(rr.x, zp0, hn0[2*q]);
                hn0[2*q+1] = fma2(rr.y, zp0, hn0[2*q+1]);
                hn1[2*q]   = fma2(rr.x, zp1, hn1[2*q]);
                hn1[2*q+1] = fma2(rr.y, zp1, hn1[2*q+1]);
            }
        }
        {
            ulonglong2* o0 = (ulonglong2*)(hout + ((size_t)b * TT + t0 + tid) * W);
            ulonglong2* o1 = (ulonglong2*)(hout + ((size_t)b * TT + t0 + tid + 256) * W);
            #pragma unroll
            for (int q = 0; q < 4; q++) {
                o0[q] = make_ulonglong2(hn0[2*q], hn0[2*q+1]);
                o1[q] = make_ulonglong2(hn1[2*q], hn1[2*q+1]);
            }
        }
    }
}

extern "C" void kernel_launch(void* const* d_in, const int* in_sizes, int n_in,
                              void* d_out, int out_size) {
    const float* x   = (const float*)d_in[0];
    const float* sw  = (const float*)d_in[1];
    const float* cw  = (const float*)d_in[2];
    const float* cb  = (const float*)d_in[3];
    const float* gw  = (const float*)d_in[4];
    const float* gb  = (const float*)d_in[5];
    const float* rw  = (const float*)d_in[6];
    const float* rb  = (const float*)d_in[7];
    const float* mix = (const float*)d_in[8];
    float* out = (float*)d_out;

    static const int dil[NL] = {1,2,4,8,16,32,64,128,256,
                                1,2,4,8,16,32,64,128,256};

    const int max_smem = (HOFF + W * (TILE2 + 2 * 256)) * (int)sizeof(float);
    cudaFuncSetAttribute(layer2_kernel,
                         cudaFuncAttributeMaxDynamicSharedMemorySize, max_smem);

    start_kernel<<<(BB * TT + 255) / 256, 256>>>(x, sw, out);

    dim3 grid(TT / TILE2, BB);
    for (int li = 0; li < NL; li++) {
        int d = dil[li];
        int smem = (HOFF + W * (TILE2 + 2 * d)) * (int)sizeof(float);
        layer2_kernel<<<grid, NTH, smem>>>(
            cw, cb, gw, gb, rw, rb, mix, out,
            li, d, (li == NL - 1) ? 1 : 0);
    }
}

// round 3
// speedup vs baseline: 1.8915x; 1.1013x over previous
#include <cuda_runtime.h>
#include <cuda_bf16.h>

#define TT   65536
#define BB   4
#define W    16
#define NL   18
#define TILE2 512
#define NTH  256
#define HOFF 1856   // float offset of h tile in dynamic smem

typedef unsigned long long u64;

__device__ float g_h0[(size_t)BB * TT * W];
__device__ float g_h1[(size_t)BB * TT * W];

__device__ __forceinline__ u64 pk2(float x){ u64 r; asm("mov.b64 %0,{%1,%1};":"=l"(r):"f"(x)); return r; }
__device__ __forceinline__ u64 pk(float lo, float hi){ u64 r; asm("mov.b64 %0,{%1,%2};":"=l"(r):"f"(lo),"f"(hi)); return r; }
__device__ __forceinline__ void unpk(u64 v, float& lo, float& hi){ asm("mov.b64 {%0,%1},%2;":"=f"(lo),"=f"(hi):"l"(v)); }
__device__ __forceinline__ u64 fma2(u64 a, u64 b, u64 c){ u64 d; asm("fma.rn.f32x2 %0,%1,%2,%3;":"=l"(d):"l"(a),"l"(b),"l"(c)); return d; }
__device__ __forceinline__ u64 mul2(u64 a, u64 b){ u64 d; asm("mul.rn.f32x2 %0,%1,%2;":"=l"(d):"l"(a),"l"(b)); return d; }
__device__ __forceinline__ u64 add2(u64 a, u64 b){ u64 d; asm("add.rn.f32x2 %0,%1,%2;":"=l"(d):"l"(a),"l"(b)); return d; }
__device__ __forceinline__ float rcpf(float x){ float r; asm("rcp.approx.f32 %0,%1;":"=f"(r):"f"(x)); return r; }

#define ABS2 0x7FFFFFFF7FFFFFFFull
#define ONE2 0x3F8000003F800000ull

// z = softsign(f)*softsign(g) = f*g / ((1+|f|)(1+|g|)), packed over 2 channels
__device__ __forceinline__ u64 ssz(u64 f, u64 g){
    u64 df = add2(f & ABS2, ONE2);
    u64 dg = add2(g & ABS2, ONE2);
    u64 dd = mul2(df, dg);
    float dl, dh; unpk(dd, dl, dh);
    u64 rr = pk(rcpf(dl), rcpf(dh));
    return mul2(mul2(f, g), rr);
}

__global__ void start_kernel(const float* __restrict__ x,
                             const float* __restrict__ sw,
                             float* __restrict__ out) {
    int idx = blockIdx.x * blockDim.x + threadIdx.x;  // over B*T
    if (idx < BB * TT) {
        float xv = x[idx];
        #pragma unroll
        for (int o = 0; o < W; o++) g_h0[(size_t)idx * W + o] = sw[o] * xv;
        out[idx] = 0.f;
    }
}

// Dynamic smem layout (floats):
//  [0    :1536)  conv+gate weights, ((k*16+i)*32 + half*16 + o); half0=f, half1=g
//  [1536 :1792)  res weights transposed rsm[i][o]
//  [1792 :1808)  mixer msm[o]
//  [1808 :1824)  conv bias, [1824:1840) gate bias, [1840:1856) res bias
//  [1856 :    )  h tile, channel-major: hT[ch][R], R = TILE2 + 2d
__global__ __launch_bounds__(NTH, 2)
void layer2_kernel(const float* __restrict__ cw, const float* __restrict__ cb,
                   const float* __restrict__ gw, const float* __restrict__ gb,
                   const float* __restrict__ rw, const float* __restrict__ rb,
                   const float* __restrict__ mix, float* __restrict__ out,
                   int li, int d, int last)
{
    extern __shared__ float sh[];
    const float* hin  = (li & 1) ? g_h1 : g_h0;
    float*       hout = (li & 1) ? g_h0 : g_h1;
    const int b   = blockIdx.y;
    const int t0  = blockIdx.x * TILE2;
    const int tid = threadIdx.x;
    const int R   = TILE2 + 2 * d;
    float* hT = sh + HOFF;

    // ---- weight prep (once per block) ----
    for (int w = tid; w < 1536; w += NTH) {
        int k = w >> 9, rem = w & 511;
        int i = rem >> 5, half = (rem >> 4) & 1, o = rem & 15;
        const float* src = half ? gw : cw;
        sh[w] = src[li * 768 + o * 48 + i * 3 + k];
    }
    if (tid < 256) {
        int i = tid >> 4, o = tid & 15;
        sh[1536 + tid] = last ? 0.f : rw[li * 256 + o * 16 + i];
    }
    if (tid < 16) {
        sh[1792 + tid] = mix[li * 16 + tid];
        sh[1808 + tid] = cb[li * 16 + tid];
        sh[1824 + tid] = gb[li * 16 + tid];
        sh[1840 + tid] = last ? 0.f : rb[li * 16 + tid];
    }

    // ---- h tile load, transposing [t][ch] -> [ch][t] ----
    {
        const int n4 = R * 4;  // float4 chunks
        for (int idx = tid; idx < n4; idx += NTH) {
            int r = idx >> 2, c = idx & 3;
            int gt = t0 - 2 * d + r;
            float4 v = make_float4(0.f, 0.f, 0.f, 0.f);
            if (gt >= 0)
                v = *(const float4*)(hin + ((size_t)b * TT + gt) * W + 4 * c);
            hT[(4 * c + 0) * R + r] = v.x;
            hT[(4 * c + 1) * R + r] = v.y;
            hT[(4 * c + 2) * R + r] = v.z;
            hT[(4 * c + 3) * R + r] = v.w;
        }
    }
    __syncthreads();

    // ---- compute: this thread owns timesteps t0+tid and t0+tid+256 ----
    const int r0 = 2 * d + tid;          // local row of ts0; ts1 = r0 + 256

    u64 f0[8], f1[8], ga0[8], ga1[8];
    {
        const u64* bp = (const u64*)(sh + 1808);
        #pragma unroll
        for (int p = 0; p < 8; p++) {
            f0[p] = bp[p];     f1[p] = bp[p];
            ga0[p] = bp[8 + p]; ga1[p] = bp[8 + p];
        }
    }

    #pragma unroll 1
    for (int k = 0; k < 3; k++) {
        const int c = r0 - (2 - k) * d;
        #pragma unroll
        for (int i = 0; i < 16; i++) {
            float hv0 = hT[i * R + c];
            float hv1 = hT[i * R + c + 256];
            u64 hp0 = pk2(hv0), hp1 = pk2(hv1);
            const ulonglong2* wp = (const ulonglong2*)(sh) + (k * 16 + i) * 8;
            #pragma unroll
            for (int q = 0; q < 4; q++) {
                ulonglong2 wf = wp[q];
                ulonglong2 wg = wp[4 + q];
                f0[2*q]   = fma2(wf.x, hp0, f0[2*q]);
                f0[2*q+1] = fma2(wf.y, hp0, f0[2*q+1]);
                f1[2*q]   = fma2(wf.x, hp1, f1[2*q]);
                f1[2*q+1] = fma2(wf.y, hp1, f1[2*q+1]);
                ga0[2*q]   = fma2(wg.x, hp0, ga0[2*q]);
                ga0[2*q+1] = fma2(wg.y, hp0, ga0[2*q+1]);
                ga1[2*q]   = fma2(wg.x, hp1, ga1[2*q]);
                ga1[2*q+1] = fma2(wg.y, hp1, ga1[2*q+1]);
            }
        }
    }

    // ---- gated activation ----
    u64 z0[8], z1[8];
    #pragma unroll
    for (int p = 0; p < 8; p++) { z0[p] = ssz(f0[p], ga0[p]); z1[p] = ssz(f1[p], ga1[p]); }

    // ---- mixer: m = sum_o mix[o]*z[o], accumulate into out ----
    {
        const u64* mp = (const u64*)(sh + 1792);
        u64 m0 = mul2(mp[0], z0[0]);
        u64 m1 = mul2(mp[0], z1[0]);
        #pragma unroll
        for (int p = 1; p < 8; p++) { m0 = fma2(mp[p], z0[p], m0); m1 = fma2(mp[p], z1[p], m1); }
        float a0, b0, a1, b1; unpk(m0, a0, b0); unpk(m1, a1, b1);
        size_t ob = (size_t)b * TT + t0 + tid;
        out[ob]       += a0 + b0;
        out[ob + 256] += a1 + b1;
    }

    // ---- residual + write next h ----
    if (!last) {
        float zf0[16], zf1[16];
        #pragma unroll
        for (int p = 0; p < 8; p++) {
            unpk(z0[p], zf0[2*p], zf0[2*p+1]);
            unpk(z1[p], zf1[2*p], zf1[2*p+1]);
        }
        // Original h re-read from GLOBAL (L2-resident, natural [t][ch] layout)
        // instead of 32 scattered LDS.32 from the transposed tile.
        u64 hn0[8], hn1[8];
        {
            const ulonglong2* s0 =
                (const ulonglong2*)(hin + ((size_t)b * TT + t0 + tid) * W);
            const ulonglong2* s1 =
                (const ulonglong2*)(hin + ((size_t)b * TT + t0 + tid + 256) * W);
            const u64* rbp = (const u64*)(sh + 1840);
            #pragma unroll
            for (int q = 0; q < 4; q++) {
                ulonglong2 a = s0[q];
                ulonglong2 c = s1[q];
                hn0[2*q]   = add2(a.x, rbp[2*q]);
                hn0[2*q+1] = add2(a.y, rbp[2*q+1]);
                hn1[2*q]   = add2(c.x, rbp[2*q]);
                hn1[2*q+1] = add2(c.y, rbp[2*q+1]);
            }
        }
        #pragma unroll
        for (int i = 0; i < 16; i++) {
            u64 zp0 = pk2(zf0[i]);
            u64 zp1 = pk2(zf1[i]);
            const ulonglong2* rp = (const ulonglong2*)(sh + 1536) + i * 4;
            #pragma unroll
            for (int q = 0; q < 4; q++) {
                ulonglong2 rr = rp[q];
                hn0[2*q]   = fma2(rr.x, zp0, hn0[2*q]);
                hn0[2*q+1] = fma2(rr.y, zp0, hn0[2*q+1]);
                hn1[2*q]   = fma2(rr.x, zp1, hn1[2*q]);
                hn1[2*q+1] = fma2(rr.y, zp1, hn1[2*q+1]);
            }
        }
        {
            ulonglong2* o0 = (ulonglong2*)(hout + ((size_t)b * TT + t0 + tid) * W);
            ulonglong2* o1 = (ulonglong2*)(hout + ((size_t)b * TT + t0 + tid + 256) * W);
            #pragma unroll
            for (int q = 0; q < 4; q++) {
                o0[q] = make_ulonglong2(hn0[2*q], hn0[2*q+1]);
                o1[q] = make_ulonglong2(hn1[2*q], hn1[2*q+1]);
            }
        }
    }
}

extern "C" void kernel_launch(void* const* d_in, const int* in_sizes, int n_in,
                              void* d_out, int out_size) {
    const float* x   = (const float*)d_in[0];
    const float* sw  = (const float*)d_in[1];
    const float* cw  = (const float*)d_in[2];
    const float* cb  = (const float*)d_in[3];
    const float* gw  = (const float*)d_in[4];
    const float* gb  = (const float*)d_in[5];
    const float* rw  = (const float*)d_in[6];
    const float* rb  = (const float*)d_in[7];
    const float* mix = (const float*)d_in[8];
    float* out = (float*)d_out;

    static const int dil[NL] = {1,2,4,8,16,32,64,128,256,
                                1,2,4,8,16,32,64,128,256};

    const int max_smem = (HOFF + W * (TILE2 + 2 * 256)) * (int)sizeof(float);
    cudaFuncSetAttribute(layer2_kernel,
                         cudaFuncAttributeMaxDynamicSharedMemorySize, max_smem);

    start_kernel<<<(BB * TT + 255) / 256, 256>>>(x, sw, out);

    dim3 grid(TT / TILE2, BB);
    for (int li = 0; li < NL; li++) {
        int d = dil[li];
        int smem = (HOFF + W * (TILE2 + 2 * d)) * (int)sizeof(float);
        layer2_kernel<<<grid, NTH, smem>>>(
            cw, cb, gw, gb, rw, rb, mix, out,
            li, d, (li == NL - 1) ? 1 : 0);
    }
}